// round 16
// baseline (speedup 1.0000x reference)
#include <cuda_runtime.h>
#include <math.h>
#include <stdint.h>

#define M_TOK 16384
#define V_DIM 4096
#define C_DIM 128
#define K_NB2 128
#define N_OPS 8

// ------------------------- scratch (device globals) -------------------------
__device__ float g_rw[V_DIM * C_DIM];           // read scores fp32
__device__ float g_rwf[C_DIM * V_DIM];          // read_w^T tf32, fragment-major chunk images
__device__ float g_wwf[V_DIM * C_DIM];          // write_w tf32, fragment-major 64-row subtile images
__device__ float g_wf[N_OPS * C_DIM * C_DIM];   // op W^T tf32, fragment-major half-K images

// ------------------------- helpers -------------------------
__device__ __forceinline__ uint32_t smem_u32(const void* p) {
    uint32_t a;
    asm("{ .reg .u64 t; cvta.to.shared.u64 t, %1; cvt.u32.u64 %0, t; }" : "=r"(a) : "l"(p));
    return a;
}
#define CP16(saddr, gptr) \
    asm volatile("cp.async.cg.shared.global [%0], [%1], 16;" :: "r"(saddr), "l"(gptr) : "memory")
#define CP_COMMIT() asm volatile("cp.async.commit_group;" ::: "memory")
template <int N> __device__ __forceinline__ void cp_wait() {
    asm volatile("cp.async.wait_group %0;" :: "n"(N) : "memory");
}
__device__ __forceinline__ float tf32r(float x) {
    float r;
    asm("cvt.rna.tf32.f32 %0, %1;" : "=f"(r) : "f"(x));
    return r;
}
__device__ __forceinline__ void mma_tf32(float c[4], const uint32_t a[4], const uint32_t b[2]) {
    asm volatile(
        "mma.sync.aligned.m16n8k8.row.col.f32.tf32.tf32.f32 "
        "{%0,%1,%2,%3},{%4,%5,%6,%7},{%8,%9},{%0,%1,%2,%3};"
        : "+f"(c[0]), "+f"(c[1]), "+f"(c[2]), "+f"(c[3])
        : "r"(a[0]), "r"(a[1]), "r"(a[2]), "r"(a[3]), "r"(b[0]), "r"(b[1]));
}
// A fragment: a0=[r][c], a1=[r+8][c], a2=[r][c+4], a3=[r+8][c+4]; lane gives r+=l/4, c+=l%4
__device__ __forceinline__ void ldfragA(uint32_t f[4], const float* base, int stride,
                                        int r0, int c0, int lane) {
    const float* p = base + (r0 + (lane >> 2)) * stride + c0 + (lane & 3);
    f[0] = __float_as_uint(p[0]);
    f[1] = __float_as_uint(p[8 * stride]);
    f[2] = __float_as_uint(p[4]);
    f[3] = __float_as_uint(p[8 * stride + 4]);
}
// B fragment (fragment-major region): lane reads float2 at region + lane*2
__device__ __forceinline__ void ldfragB(uint32_t b[2], const float* region, int lane) {
    float2 v = *(const float2*)(region + lane * 2);
    b[0] = __float_as_uint(v.x);
    b[1] = __float_as_uint(v.y);
}

// fragment-major float-index for a B-style tile with KB k-blocks per n-block row
__device__ __forceinline__ int fragidx(int n, int k, int kblocks) {
    return (((n >> 3) * kblocks + (k >> 3)) << 6) + (((n & 7) * 4 + (k & 3)) << 1) + ((k & 7) >> 2);
}

// ---------------------------------------------------------------------------
// Addressing GEMM: scores = basis(4096x128) @ coeff(128x128)^T
// z=0: rcoef -> g_rw fp32 ; z=1: wcoef -> g_wwf (tf32, frag-major 64-row subtiles)
// ---------------------------------------------------------------------------
__global__ __launch_bounds__(256) void sgemm_addr(
    const float* __restrict__ A, const float* __restrict__ B0,
    const float* __restrict__ B1)
{
    __shared__ float As[16][128];
    __shared__ float Bs[16][128];
    const int tid = threadIdx.x;
    const int tc = tid % 16, tr = tid / 16;
    const int m0 = blockIdx.y * 128;
    const int path = blockIdx.z;
    const float* B = path ? B1 : B0;

    float acc[8][8];
#pragma unroll
    for (int i = 0; i < 8; i++)
#pragma unroll
        for (int j = 0; j < 8; j++) acc[i][j] = 0.0f;

    for (int k0 = 0; k0 < K_NB2; k0 += 16) {
#pragma unroll
        for (int i = 0; i < 2; i++) {
            int idx = tid + i * 256;
            int row = idx / 4, c4 = idx % 4;
            float4 va = *(const float4*)&A[(size_t)(m0 + row) * K_NB2 + k0 + c4 * 4];
            As[c4 * 4 + 0][row] = va.x; As[c4 * 4 + 1][row] = va.y;
            As[c4 * 4 + 2][row] = va.z; As[c4 * 4 + 3][row] = va.w;
            float4 vb = *(const float4*)&B[(size_t)row * K_NB2 + k0 + c4 * 4];
            Bs[c4 * 4 + 0][row] = vb.x; Bs[c4 * 4 + 1][row] = vb.y;
            Bs[c4 * 4 + 2][row] = vb.z; Bs[c4 * 4 + 3][row] = vb.w;
        }
        __syncthreads();
#pragma unroll
        for (int k = 0; k < 16; k++) {
            float ra[8], rb[8];
#pragma unroll
            for (int i = 0; i < 8; i++) ra[i] = As[k][tr * 8 + i];
#pragma unroll
            for (int j = 0; j < 8; j++) rb[j] = Bs[k][tc * 8 + j];
#pragma unroll
            for (int i = 0; i < 8; i++)
#pragma unroll
                for (int j = 0; j < 8; j++) acc[i][j] += ra[i] * rb[j];
        }
        __syncthreads();
    }
#pragma unroll
    for (int i = 0; i < 8; i++) {
        const int n = m0 + tr * 8 + i;
        if (path == 0) {
#pragma unroll
            for (int j = 0; j < 8; j++) g_rw[(size_t)n * C_DIM + tc * 8 + j] = acc[i][j];
        } else {
            // g_wwf: [nt=n>>6] 32KB images: 64n x 128k frag-major (16 k-blocks)
            const int nt = n >> 6, np = n & 63;
#pragma unroll
            for (int j = 0; j < 8; j++) {
                int k = tc * 8 + j;
                g_wwf[nt * 8192 + fragidx(np, k, 16)] = tf32r(acc[i][j]);
            }
        }
    }
}

// ---------------------------------------------------------------------------
// Column softmax over V (axis 0); write g_rwf: [ch=v>>6] 32KB images:
// 128c x 64k frag-major (8 k-blocks), tf32-rounded.
// ---------------------------------------------------------------------------
__global__ __launch_bounds__(256) void col_softmax_T()
{
    __shared__ float col[V_DIM];
    __shared__ float red[256];
    const int c = blockIdx.x;
    const int tid = threadIdx.x;

    float m = -1e30f;
    for (int v = tid; v < V_DIM; v += 256) {
        float x = g_rw[(size_t)v * C_DIM + c];
        col[v] = x;
        m = fmaxf(m, x);
    }
    red[tid] = m; __syncthreads();
    for (int s = 128; s > 0; s >>= 1) { if (tid < s) red[tid] = fmaxf(red[tid], red[tid + s]); __syncthreads(); }
    m = red[0]; __syncthreads();

    float sum = 0.0f;
    for (int v = tid; v < V_DIM; v += 256) { float e = expf(col[v] - m); col[v] = e; sum += e; }
    red[tid] = sum; __syncthreads();
    for (int s = 128; s > 0; s >>= 1) { if (tid < s) red[tid] += red[tid + s]; __syncthreads(); }
    const float inv = 1.0f / red[0];

    for (int v = tid; v < V_DIM; v += 256) {
        g_rwf[(v >> 6) * 8192 + fragidx(c, v & 63, 8)] = tf32r(col[v] * inv);
    }
}

// op weights [op][k][n] -> g_wf: [op][kh] 32KB images: 128n x 64k frag-major
__global__ __launch_bounds__(256) void prep_wT(const float* __restrict__ W)
{
    int idx = blockIdx.x * 256 + threadIdx.x;
    int op = idx >> 14;
    int rem = idx & 16383;
    int n = rem >> 7, k = rem & 127;
    float v = W[op * 16384 + k * 128 + n];
    g_wf[(op * 2 + (k >> 6)) * 8192 + fragidx(n, k & 63, 8)] = tf32r(v);
}

// ---------------------------------------------------------------------------
// MEGA kernel (tf32 single-pass), 512 threads, 16 warps 4x4 (tiles 32x32).
// Dynamic smem 167936B:
//   A stages (phase1 x-chunk, 128x64 fp32, stride 68 floats): s*34816, s=0,1
//   B slots: 69632 + slot*32768, slot=0..2 (ph1 depth-2; ph2/3 use slots 1,2 depth-1)
//   vals/mix: offset 0 (128 x 132-float rows = 67584B, fits in A region)
// ---------------------------------------------------------------------------
__global__ __launch_bounds__(512, 1) void mega(
    const float* __restrict__ x, const float* __restrict__ logits,
    const float* __restrict__ bias, float* __restrict__ out,
    const float* __restrict__ oscale)
{
    extern __shared__ char sm[];
    __shared__ float bs[N_OPS * C_DIM];
    const uint32_t sb = smem_u32(sm);
    const int tid = threadIdx.x, lane = tid & 31, wid = tid >> 5;
    const int wr = wid & 3, wc = wid >> 2;      // 4x4
    const int m0 = blockIdx.x * 128;
    const float* xbase = x + (size_t)m0 * V_DIM;

#pragma unroll
    for (int i = 0; i < 2; i++) bs[tid + i * 512] = bias[tid + i * 512];
    float wv[N_OPS];
    float mx = -1e30f;
#pragma unroll
    for (int i = 0; i < N_OPS; i++) { wv[i] = __ldg(&logits[i]); mx = fmaxf(mx, wv[i]); }
    float sumw = 0.0f;
#pragma unroll
    for (int i = 0; i < N_OPS; i++) { wv[i] = expf(wv[i] - mx); sumw += wv[i]; }
#pragma unroll
    for (int i = 0; i < N_OPS; i++) wv[i] /= sumw;

    float* vals = (float*)sm;                    // stride 132 floats

    // =========================== PHASE 1 ===========================
    {
        float4 apf[4];
        float acc[2][4][4];
#pragma unroll
        for (int a = 0; a < 2; a++)
#pragma unroll
            for (int b = 0; b < 4; b++)
#pragma unroll
                for (int c = 0; c < 4; c++) acc[a][b][c] = 0.0f;

        auto ldA = [&](int k0) {
#pragma unroll
            for (int i = 0; i < 4; i++) {
                int idx = tid + i * 512;
                apf[i] = *(const float4*)&xbase[(size_t)(idx >> 4) * V_DIM + k0 + (idx & 15) * 4];
            }
        };
        auto stA = [&](int s) {
            char* a = sm + s * 34816;
#pragma unroll
            for (int i = 0; i < 4; i++) {
                int idx = tid + i * 512;
                int r = idx >> 4, c4 = idx & 15;
                float4 v;
                v.x = tf32r(apf[i].x); v.y = tf32r(apf[i].y);
                v.z = tf32r(apf[i].z); v.w = tf32r(apf[i].w);
                *(float4*)(a + r * 272 + c4 * 16) = v;
            }
        };
        auto ldB = [&](int ch, int slot) {
            uint32_t dst = sb + 69632 + slot * 32768;
            const char* src = (const char*)(g_rwf + ch * 8192);
#pragma unroll
            for (int i = 0; i < 4; i++) {
                int idx = tid + i * 512;
                CP16(dst + idx * 16, src + idx * 16);
            }
        };

        ldA(0);
        stA(0);
        ldB(0, 0); CP_COMMIT();
        ldB(1, 1); CP_COMMIT();
        ldA(64);

        for (int ch = 0; ch < 64; ch++) {
            const int s = ch & 1;
            if (ch < 63) cp_wait<1>(); else cp_wait<0>();
            __syncthreads();
            if (ch < 63) stA(1 - s);
            if (ch < 62) { ldB(ch + 2, (ch + 2) % 3); CP_COMMIT(); ldA((ch + 2) * 64); }

            const float* As = (const float*)(sm + s * 34816);
            const float* Bst = (const float*)(sm + 69632 + (ch % 3) * 32768);
#pragma unroll
            for (int kb = 0; kb < 8; kb++) {
                uint32_t Af[2][4], Bf[4][2];
#pragma unroll
                for (int mf = 0; mf < 2; mf++)
                    ldfragA(Af[mf], As, 68, wr * 32 + mf * 16, kb * 8, lane);
#pragma unroll
                for (int nf = 0; nf < 4; nf++)
                    ldfragB(Bf[nf], Bst + (((wc * 4 + nf) * 8 + kb) << 6), lane);
#pragma unroll
                for (int mf = 0; mf < 2; mf++)
#pragma unroll
                    for (int nf = 0; nf < 4; nf++)
                        mma_tf32(acc[mf][nf], Af[mf], Bf[nf]);
            }
        }
        __syncthreads();    // all reads of A region + B slots done

        // vals -> smem (fp32, tf32-rounded), A region
#pragma unroll
        for (int mf = 0; mf < 2; mf++)
#pragma unroll
            for (int nf = 0; nf < 4; nf++) {
                int r = wr * 32 + mf * 16 + (lane >> 2);
                int c = wc * 32 + nf * 8 + 2 * (lane & 3);
                *(float2*)&vals[r * 132 + c] =
                    make_float2(tf32r(acc[mf][nf][0]), tf32r(acc[mf][nf][1]));
                *(float2*)&vals[(r + 8) * 132 + c] =
                    make_float2(tf32r(acc[mf][nf][2]), tf32r(acc[mf][nf][3]));
            }
        // prefetch W (op0, kh0) -> slot1
        {
            uint32_t dst = sb + 69632 + 1 * 32768;
            const char* src = (const char*)g_wf;
#pragma unroll
            for (int i = 0; i < 4; i++) {
                int idx = tid + i * 512;
                CP16(dst + idx * 16, src + idx * 16);
            }
            CP_COMMIT();
        }
        __syncthreads();
    }

    // =========================== PHASE 2 ===========================
    float res[2][4][4];
#pragma unroll
    for (int a = 0; a < 2; a++)
#pragma unroll
        for (int b = 0; b < 4; b++)
#pragma unroll
            for (int c = 0; c < 4; c++) res[a][b][c] = 0.0f;

    {
        float acc[2][4][4];
        auto ldW = [&](int it, int slot) {
            uint32_t dst = sb + 69632 + slot * 32768;
            const char* src = (const char*)(g_wf + it * 8192);
#pragma unroll
            for (int i = 0; i < 4; i++) {
                int idx = tid + i * 512;
                CP16(dst + idx * 16, src + idx * 16);
            }
        };

#pragma unroll 1
        for (int it = 0; it < 16; it++) {
            const int op = it >> 1, kh = it & 1;
            const int slot = 1 + (it & 1);
            cp_wait<0>();
            __syncthreads();
            if (it < 15) { ldW(it + 1, 1 + ((it + 1) & 1)); CP_COMMIT(); }

            if (kh == 0) {
#pragma unroll
                for (int a = 0; a < 2; a++)
#pragma unroll
                    for (int b = 0; b < 4; b++)
#pragma unroll
                        for (int c = 0; c < 4; c++) acc[a][b][c] = 0.0f;
            }

            const float* Wst = (const float*)(sm + 69632 + slot * 32768);
#pragma unroll
            for (int kb = 0; kb < 8; kb++) {
                uint32_t Af[2][4], Bf[4][2];
#pragma unroll
                for (int mf = 0; mf < 2; mf++)
                    ldfragA(Af[mf], vals, 132, wr * 32 + mf * 16, kh * 64 + kb * 8, lane);
#pragma unroll
                for (int nf = 0; nf < 4; nf++)
                    ldfragB(Bf[nf], Wst + (((wc * 4 + nf) * 8 + kb) << 6), lane);
#pragma unroll
                for (int mf = 0; mf < 2; mf++)
#pragma unroll
                    for (int nf = 0; nf < 4; nf++)
                        mma_tf32(acc[mf][nf], Af[mf], Bf[nf]);
            }
            if (kh == 1) {
                const float w = wv[op];
#pragma unroll
                for (int mf = 0; mf < 2; mf++)
#pragma unroll
                    for (int nf = 0; nf < 4; nf++)
#pragma unroll
                        for (int j = 0; j < 4; j++) {
                            int col = wc * 32 + nf * 8 + 2 * (lane & 3) + (j & 1);
                            float v = acc[mf][nf][j] + bs[op * C_DIM + col];
                            float f;
                            switch (op) {
                                case 0: f = v; break;
                                case 1: f = fmaxf(v, 0.0f); break;
                                case 2: f = 0.5f * v * (1.0f + erff(v * 0.70710678118654752f)); break;
                                case 3: f = v * v; break;
                                case 4: f = -v; break;
                                case 5: f = fabsf(v); break;
                                case 6: f = tanhf(v); break;
                                default: f = 1.0f / (1.0f + expf(-v)); break;
                            }
                            res[mf][nf][j] += w * f;
                        }
            }
        }
    }

    // mix -> vals region (after ALL phase-2 reads)
    __syncthreads();
#pragma unroll
    for (int mf = 0; mf < 2; mf++)
#pragma unroll
        for (int nf = 0; nf < 4; nf++) {
            int r = wr * 32 + mf * 16 + (lane >> 2);
            int c = wc * 32 + nf * 8 + 2 * (lane & 3);
            *(float2*)&vals[r * 132 + c] =
                make_float2(tf32r(res[mf][nf][0]), tf32r(res[mf][nf][1]));
            *(float2*)&vals[(r + 8) * 132 + c] =
                make_float2(tf32r(res[mf][nf][2]), tf32r(res[mf][nf][3]));
        }
    // prefetch write_w subtile 0 -> slot1
    {
        uint32_t dst = sb + 69632 + 1 * 32768;
        const char* src = (const char*)g_wwf;
#pragma unroll
        for (int i = 0; i < 4; i++) {
            int idx = tid + i * 512;
            CP16(dst + idx * 16, src + idx * 16);
        }
        CP_COMMIT();
    }
    __syncthreads();

    // =========================== PHASE 3 ===========================
    // out(128 x 4096) = mix @ write_w^T * alpha ; 64 subtiles of 64 N-cols
    // warp tiles 32x16 (4x4 grid over 128x64)
    {
        const float alpha = __ldg(oscale);
        auto ldWW = [&](int nt, int slot) {
            uint32_t dst = sb + 69632 + slot * 32768;
            const char* src = (const char*)(g_wwf + nt * 8192);
#pragma unroll
            for (int i = 0; i < 4; i++) {
                int idx = tid + i * 512;
                CP16(dst + idx * 16, src + idx * 16);
            }
        };

#pragma unroll 1
        for (int nt = 0; nt < 64; nt++) {
            const int slot = 1 + (nt & 1);
            cp_wait<0>();
            __syncthreads();
            if (nt < 63) { ldWW(nt + 1, 1 + ((nt + 1) & 1)); CP_COMMIT(); }

            float acc[2][2][4];
#pragma unroll
            for (int a = 0; a < 2; a++)
#pragma unroll
                for (int b = 0; b < 2; b++)
#pragma unroll
                    for (int c = 0; c < 4; c++) acc[a][b][c] = 0.0f;

            const float* Bst = (const float*)(sm + 69632 + slot * 32768);
#pragma unroll
            for (int kb = 0; kb < 16; kb++) {
                uint32_t Af[2][4], Bf[2][2];
#pragma unroll
                for (int mf = 0; mf < 2; mf++)
                    ldfragA(Af[mf], vals, 132, wr * 32 + mf * 16, kb * 8, lane);
#pragma unroll
                for (int nf = 0; nf < 2; nf++)
                    ldfragB(Bf[nf], Bst + (((wc * 2 + nf) * 16 + kb) << 6), lane);
#pragma unroll
                for (int mf = 0; mf < 2; mf++)
#pragma unroll
                    for (int nf = 0; nf < 2; nf++)
                        mma_tf32(acc[mf][nf], Af[mf], Bf[nf]);
            }
#pragma unroll
            for (int mf = 0; mf < 2; mf++)
#pragma unroll
                for (int nf = 0; nf < 2; nf++) {
                    int r = m0 + wr * 32 + mf * 16 + (lane >> 2);
                    int c = nt * 64 + wc * 16 + nf * 8 + 2 * (lane & 3);
                    float2 v0 = make_float2(acc[mf][nf][0] * alpha, acc[mf][nf][1] * alpha);
                    float2 v1 = make_float2(acc[mf][nf][2] * alpha, acc[mf][nf][3] * alpha);
                    *(float2*)&out[(size_t)r * V_DIM + c] = v0;
                    *(float2*)&out[(size_t)(r + 8) * V_DIM + c] = v1;
                }
        }
    }
}

// ---------------------------------------------------------------------------
extern "C" void kernel_launch(void* const* d_in, const int* in_sizes, int n_in,
                              void* d_out, int out_size)
{
    const float* x      = (const float*)d_in[0];
    const float* basis  = (const float*)d_in[1];
    const float* rcoef  = (const float*)d_in[2];
    const float* wcoef  = (const float*)d_in[3];
    const float* logits = (const float*)d_in[4];
    const float* opW    = (const float*)d_in[5];
    const float* opB    = (const float*)d_in[6];
    const float* oscale = (const float*)d_in[7];
    float* out = (float*)d_out;

    static bool attr_done = false;
    if (!attr_done) {
        cudaFuncSetAttribute(mega, cudaFuncAttributeMaxDynamicSharedMemorySize, 167936);
        attr_done = true;
    }

    sgemm_addr<<<dim3(1, V_DIM / 128, 2), 256>>>(basis, rcoef, wcoef);
    col_softmax_T<<<C_DIM, 256>>>();
    prep_wT<<<N_OPS * C_DIM * C_DIM / 256, 256>>>(opW);
    mega<<<M_TOK / 128, 512, 167936>>>(x, logits, opB, out, oscale);
}